// round 7
// baseline (speedup 1.0000x reference)
#include <cuda_runtime.h>
#include <cuda_fp16.h>
#include <cstdint>

#define T_STEPS 64
#define B_DIM   32
#define W_DIM   1024
#define L_DIM   4
#define G_DIM   4096
#define NB      64
#define NT      256
#define KCH     256
#define NCH     8            // 2048 / 256
#define ROWH    264          // 256 + 8 pad halfs

#define A_BYTES (64 * ROWH * 2)             // 33792 (64 M-rows)
#define B_BYTES (32 * ROWH * 2)             // 16896 (32 batches)
#define STAGE_BYTES (A_BYTES + B_BYTES)     // 50688
#define RED_OFF (2 * STAGE_BYTES)           // RED aliases stage2
#define DYN_BYTES (3 * STAGE_BYTES)         // 152064

__device__ __half g_W16[2][L_DIM][G_DIM][W_DIM];   // transposed fp16 weights (64 MB)
__device__ __half g_x16[T_STEPS][B_DIM][W_DIM];    // fp16 input
__device__ __half g_h16[L_DIM][B_DIM][W_DIM];      // layer-forward h (unmasked)
__device__ __half g_hm16[2][L_DIM][B_DIM][W_DIM];  // pre-masked recurrent h
__device__ float  g_c[L_DIM][B_DIM][W_DIM];        // pre-masked c
__device__ unsigned g_count = 0;
__device__ unsigned g_gen   = 0;

static __device__ __forceinline__ unsigned smem_u32(const void* p) {
    return (unsigned)__cvta_generic_to_shared(p);
}

__device__ __forceinline__ void gridBarrier() {
    __syncthreads();
    if (threadIdx.x == 0) {
        volatile unsigned* genp = &g_gen;
        unsigned my = *genp;
        __threadfence();
        unsigned arrived = atomicAdd(&g_count, 1);
        if (arrived == NB - 1) {
            atomicExch(&g_count, 0);
            __threadfence();
            *genp = my + 1;
        } else {
            while (*genp == my) { }
        }
        __threadfence();
    }
    __syncthreads();
}

__device__ __forceinline__ void cpa16(unsigned dst, const void* src) {
    asm volatile("cp.async.cg.shared.global [%0], [%1], 16;" :: "r"(dst), "l"(src));
}
#define CP_COMMIT() asm volatile("cp.async.commit_group;" ::: "memory")

#define LDSM4(r0, r1, r2, r3, addr) \
    asm volatile("ldmatrix.sync.aligned.m8n8.x4.shared.b16 {%0,%1,%2,%3}, [%4];" \
                 : "=r"(r0), "=r"(r1), "=r"(r2), "=r"(r3) : "r"(addr))

__device__ __forceinline__ void mma_f16(float& c0, float& c1, float& c2, float& c3,
                                        unsigned a0, unsigned a1, unsigned a2, unsigned a3,
                                        unsigned b0, unsigned b1) {
    asm volatile(
        "mma.sync.aligned.m16n8k16.row.col.f32.f16.f16.f32 "
        "{%0,%1,%2,%3}, {%4,%5,%6,%7}, {%8,%9}, {%0,%1,%2,%3};"
        : "+f"(c0), "+f"(c1), "+f"(c2), "+f"(c3)
        : "r"(a0), "r"(a1), "r"(a2), "r"(a3), "r"(b0), "r"(b1));
}

__device__ __forceinline__ float sigmoidf_(float v) { return 1.0f / (1.0f + expf(-v)); }

// ---------------- one-time converts ----------------
__global__ void convert_w_kernel(const float* __restrict__ Wx, const float* __restrict__ Wh) {
    __shared__ float tile[32][33];
    const int w = blockIdx.z >> 2, l = blockIdx.z & 3;
    const float* src = (w ? Wh : Wx) + (size_t)l * W_DIM * G_DIM;
    const int c0 = blockIdx.x * 32, k0 = blockIdx.y * 32;
    const int tx = threadIdx.x, ty = threadIdx.y;   // 32 x 8
    #pragma unroll
    for (int i = 0; i < 4; i++)
        tile[ty + 8 * i][tx] = src[(size_t)(k0 + ty + 8 * i) * G_DIM + c0 + tx];
    __syncthreads();
    __half* dst = &g_W16[w][l][0][0];
    #pragma unroll
    for (int i = 0; i < 4; i++)
        dst[(size_t)(c0 + ty + 8 * i) * W_DIM + k0 + tx] = __float2half(tile[tx][ty + 8 * i]);
}

__global__ void convert_x_kernel(const float* __restrict__ x) {
    __half* dst = &g_x16[0][0][0];
    int i = blockIdx.x * blockDim.x + threadIdx.x;
    #pragma unroll
    for (int r = 0; r < 8; ++r) {
        int idx = i + r * (gridDim.x * blockDim.x);
        if (idx < T_STEPS * B_DIM * W_DIM) dst[idx] = __float2half(x[idx]);
    }
}

#define RED_IDX(ks, m, n) ((((ks) * 64 + (m)) * 36) + (n))

__global__ __launch_bounds__(NT) void lstm_mma_kernel(
    const void*  __restrict__ resets_raw,
    const float* __restrict__ c0,
    const float* __restrict__ h0,
    const float* __restrict__ bias,
    float* __restrict__ out)
{
    extern __shared__ __align__(16) char pool[];
    __shared__ float mask_next[B_DIM];
    __shared__ int s_rmode;

    const int tid  = threadIdx.x;
    const int cta  = blockIdx.x;
    const int lane = tid & 31;
    const int w    = tid >> 5;
    const int ks   = w & 3;           // k-slice 0..3 (64 k each)
    const int ms   = w >> 2;          // m-slice 0..1 (32 rows each)
    const int u0   = cta * 16;        // 16 units per CTA

    float* out_ys = out;
    float* out_cs = out + (size_t)T_STEPS * B_DIM * W_DIM;
    float* out_hs = out_cs + (size_t)L_DIM * B_DIM * W_DIM;

    if (tid == 0) {
        const unsigned char* rb = (const unsigned char*)resets_raw;
        int s1 = 0, s2 = 0, s3 = 0;
        for (int i = 0; i < T_STEPS * B_DIM; i += 4) { s1 += rb[i+1]; s2 += rb[i+2]; s3 += rb[i+3]; }
        s_rmode = (s1 > 0) ? 0 : ((s2 == 0 && s3 == 0) ? 1 : 2);
    }
    __syncthreads();
    const int rmode = s_rmode;

    const unsigned char* r8  = (const unsigned char*)resets_raw;
    const int*           r32 = (const int*)resets_raw;
    const float*         rf  = (const float*)resets_raw;
    #define KEEP(t, b) (rmode == 0 ? (r8[(t)*B_DIM+(b)] ? 0.0f : 1.0f) \
                      : rmode == 1 ? (r32[(t)*B_DIM+(b)] ? 0.0f : 1.0f) \
                                   : (rf[(t)*B_DIM+(b)] != 0.0f ? 0.0f : 1.0f))

    // ---- init state (pre-masked with keep[0]) ----
    for (int i = cta * NT + tid; i < L_DIM * B_DIM * W_DIM; i += NB * NT) {
        int b = (i >> 10) & 31;
        float k0f = KEEP(0, b);
        (&g_hm16[0][0][0][0])[i] = __float2half(k0f * h0[i]);
        (&g_c[0][0][0])[i]       = k0f * c0[i];
    }
    gridBarrier();

    const unsigned poolAddr = smem_u32(pool);
    float* red = (float*)(pool + RED_OFF);

    // ---- staging offset tables ----
    unsigned wOffK[8], aDst[8], bSrcK[4], bDst[4];
    #pragma unroll
    for (int i = 0; i < 8; ++i) {
        int o = tid + NT * i;              // 0..2047
        int m = o >> 5, kq = o & 31;       // m-row, 8-half quantum
        wOffK[i] = (unsigned)(((m >> 4) * 1024 + u0 + (m & 15)) * W_DIM + kq * 8);
        aDst[i]  = (unsigned)((m * ROWH + kq * 8) * 2);
    }
    #pragma unroll
    for (int i = 0; i < 4; ++i) {
        int o = tid + NT * i;              // 0..1023
        int n = o >> 5, kq = o & 31;
        bSrcK[i] = (unsigned)(n * W_DIM + kq * 8);
        bDst[i]  = (unsigned)(A_BYTES + (n * ROWH + kq * 8) * 2);
    }

    #define STAGE_W(sidx, wb, kc) do { \
        const unsigned _b = poolAddr + (sidx) * STAGE_BYTES; \
        _Pragma("unroll") \
        for (int _i = 0; _i < 8; ++_i) cpa16(_b + aDst[_i], (wb) + wOffK[_i] + (kc)); \
    } while (0)
    #define STAGE_A(sidx, ab, kc) do { \
        const unsigned _b = poolAddr + (sidx) * STAGE_BYTES; \
        _Pragma("unroll") \
        for (int _i = 0; _i < 4; ++_i) cpa16(_b + bDst[_i], (ab) + bSrcK[_i] + (kc)); \
    } while (0)

    // ---- fragment ldmatrix offsets ----
    const int kb     = ks * 64;                         // warp k base (halfs)
    const int mbase  = ms * 32;
    const int lrow8  = (lane & 7);
    const unsigned aoff0 = (unsigned)(((mbase +      lrow8 + ((lane >> 3) & 1) * 8) * ROWH
                                       + ((lane >> 4) & 1) * 8) * 2);
    const unsigned aoff1 = aoff0 + 16 * ROWH * 2;
    const unsigned boff0 = (unsigned)(((lrow8 + ((lane >> 4) & 1) * 8) * ROWH
                                       + ((lane >> 3) & 1) * 8) * 2);
    const unsigned boff1 = boff0 + 16 * ROWH * 2;

    const int row = lane >> 2;
    const int kc2 = (lane & 3) * 2;

    // ---- prime pipeline for phase 0: weights chunks 0,1 ----
    {
        const __half* wX0 = &g_W16[0][0][0][0];
        STAGE_W(0, wX0, 0);   CP_COMMIT();
        STAGE_W(1, wX0, 256); CP_COMMIT();
    }

    for (int t = 0; t < T_STEPS; ++t) {
        if (tid < B_DIM)
            mask_next[tid] = (t + 1 < T_STEPS) ? KEEP(t + 1, tid) : 1.0f;

        for (int l = 0; l < L_DIM; ++l) {
            const __half* wX = &g_W16[0][l][0][0];
            const __half* wH = &g_W16[1][l][0][0];
            const __half* ax = (l == 0) ? &g_x16[t][0][0] : &g_h16[l - 1][0][0];
            const __half* ah = &g_hm16[t & 1][l][0][0];

            // acts for chunks 0,1 + full chunk 2
            STAGE_A(0, ax, 0);   CP_COMMIT();
            STAGE_A(1, ax, 256); CP_COMMIT();
            STAGE_W(2, ax == ax ? wX : wX, 512); STAGE_A(2, ax, 512); CP_COMMIT();

            float acc[2][4][4];
            #pragma unroll
            for (int mt = 0; mt < 2; ++mt)
                #pragma unroll
                for (int nt = 0; nt < 4; ++nt)
                    #pragma unroll
                    for (int q = 0; q < 4; ++q) acc[mt][nt][q] = 0.0f;

            for (int c = 0; c < NCH; ++c) {
                if (c < 6)       asm volatile("cp.async.wait_group 2;" ::: "memory");
                else if (c == 6) asm volatile("cp.async.wait_group 1;" ::: "memory");
                else             asm volatile("cp.async.wait_group 0;" ::: "memory");
                __syncthreads();

                // ---- compute chunk c ----
                const unsigned asb = poolAddr + (c % 3) * STAGE_BYTES;
                const unsigned bsb = asb + A_BYTES;
                #pragma unroll
                for (int s = 0; s < 4; ++s) {
                    const unsigned kByte = (unsigned)((kb + s * 16) * 2);
                    unsigned a0[4], a1[4], b0[4], b1[4];
                    LDSM4(a0[0], a0[1], a0[2], a0[3], asb + aoff0 + kByte);
                    LDSM4(a1[0], a1[1], a1[2], a1[3], asb + aoff1 + kByte);
                    LDSM4(b0[0], b0[1], b0[2], b0[3], bsb + boff0 + kByte);
                    LDSM4(b1[0], b1[1], b1[2], b1[3], bsb + boff1 + kByte);
                    mma_f16(acc[0][0][0], acc[0][0][1], acc[0][0][2], acc[0][0][3],
                            a0[0], a0[1], a0[2], a0[3], b0[0], b0[1]);
                    mma_f16(acc[0][1][0], acc[0][1][1], acc[0][1][2], acc[0][1][3],
                            a0[0], a0[1], a0[2], a0[3], b0[2], b0[3]);
                    mma_f16(acc[0][2][0], acc[0][2][1], acc[0][2][2], acc[0][2][3],
                            a0[0], a0[1], a0[2], a0[3], b1[0], b1[1]);
                    mma_f16(acc[0][3][0], acc[0][3][1], acc[0][3][2], acc[0][3][3],
                            a0[0], a0[1], a0[2], a0[3], b1[2], b1[3]);
                    mma_f16(acc[1][0][0], acc[1][0][1], acc[1][0][2], acc[1][0][3],
                            a1[0], a1[1], a1[2], a1[3], b0[0], b0[1]);
                    mma_f16(acc[1][1][0], acc[1][1][1], acc[1][1][2], acc[1][1][3],
                            a1[0], a1[1], a1[2], a1[3], b0[2], b0[3]);
                    mma_f16(acc[1][2][0], acc[1][2][1], acc[1][2][2], acc[1][2][3],
                            a1[0], a1[1], a1[2], a1[3], b1[0], b1[1]);
                    mma_f16(acc[1][3][0], acc[1][3][1], acc[1][3][2], acc[1][3][3],
                            a1[0], a1[1], a1[2], a1[3], b1[2], b1[3]);
                }
                __syncthreads();

                if (c + 3 < NCH) {
                    const int cn = c + 3;
                    const __half* wb = (cn < 4) ? wX : wH;
                    const __half* ab = (cn < 4) ? ax : ah;
                    const unsigned kc = (unsigned)((cn & 3) * 256);
                    STAGE_W(cn % 3, wb, kc);
                    STAGE_A(cn % 3, ab, kc);
                    CP_COMMIT();
                }
            }

            // ---- prefetch next phase's weight chunks 0,1 (independent of barrier) ----
            if (!(t == T_STEPS - 1 && l == L_DIM - 1)) {
                const int ln = (l + 1) & 3;
                const __half* wXn = &g_W16[0][ln][0][0];
                STAGE_W(0, wXn, 0);   CP_COMMIT();
                STAGE_W(1, wXn, 256); CP_COMMIT();
            }

            // ---- partial-sum exchange over k-slices ----
            #pragma unroll
            for (int mt = 0; mt < 2; ++mt)
                #pragma unroll
                for (int nt = 0; nt < 4; ++nt) {
                    const int m_r = mbase + mt * 16 + row;
                    const int n0  = nt * 8 + kc2;
                    *(float2*)&red[RED_IDX(ks, m_r, n0)] =
                        make_float2(acc[mt][nt][0], acc[mt][nt][1]);
                    *(float2*)&red[RED_IDX(ks, m_r + 8, n0)] =
                        make_float2(acc[mt][nt][2], acc[mt][nt][3]);
                }
            __syncthreads();

            // ---- reduce + bias + LSTM pointwise ----
            {
                const int j  = tid & 15;       // unit within CTA
                const int n0 = tid >> 4;       // 0..15
                const int u  = u0 + j;
                #pragma unroll
                for (int h = 0; h < 2; ++h) {
                    const int n = n0 + 16 * h;
                    float gate[4];
                    #pragma unroll
                    for (int g = 0; g < 4; ++g) {
                        float s = bias[l * G_DIM + g * W_DIM + u0 + j];
                        #pragma unroll
                        for (int kk = 0; kk < 4; ++kk)
                            s += red[RED_IDX(kk, g * 16 + j, n)];
                        gate[g] = s;
                    }
                    float cOld = g_c[l][n][u];
                    float cN = sigmoidf_(gate[1]) * cOld + sigmoidf_(gate[0]) * tanhf(gate[2]);
                    float hN = sigmoidf_(gate[3]) * tanhf(cN);
                    float keepN = mask_next[n];

                    g_c[l][n][u]   = keepN * cN;
                    g_h16[l][n][u] = __float2half(hN);
                    g_hm16[(t + 1) & 1][l][n][u] = __float2half(keepN * hN);
                    if (l == L_DIM - 1)
                        out_ys[((size_t)t * B_DIM + n) * W_DIM + u] = hN;
                    if (t == T_STEPS - 1) {
                        out_cs[((size_t)l * B_DIM + n) * W_DIM + u] = cN;
                        out_hs[((size_t)l * B_DIM + n) * W_DIM + u] = hN;
                    }
                }
            }
            gridBarrier();
        }
    }
    #undef KEEP
}

extern "C" void kernel_launch(void* const* d_in, const int* in_sizes, int n_in,
                              void* d_out, int out_size) {
    const float* x      = (const float*)d_in[0];
    const void*  resets = (const void*) d_in[1];
    const float* c0     = (const float*)d_in[2];
    const float* h0     = (const float*)d_in[3];
    const float* Wx     = (const float*)d_in[4];
    const float* Wh     = (const float*)d_in[5];
    const float* b      = (const float*)d_in[6];
    (void)in_sizes; (void)n_in; (void)out_size;

    static int configured = 0;
    if (!configured) {
        cudaFuncSetAttribute(lstm_mma_kernel, cudaFuncAttributeMaxDynamicSharedMemorySize, DYN_BYTES);
        configured = 1;
    }

    convert_w_kernel<<<dim3(G_DIM / 32, W_DIM / 32, 8), dim3(32, 8)>>>(Wx, Wh);
    convert_x_kernel<<<1024, 256>>>(x);
    lstm_mma_kernel<<<NB, NT, DYN_BYTES>>>(resets, c0, h0, b, (float*)d_out);
}

// round 8
// speedup vs baseline: 1.2447x; 1.2447x over previous
#include <cuda_runtime.h>
#include <cuda_fp16.h>
#include <cstdint>

#define T_STEPS 64
#define B_DIM   32
#define W_DIM   1024
#define L_DIM   4
#define G_DIM   4096
#define NB      128
#define NT      256
#define KCH     128
#define NCH     16
#define STAGES  4
#define ROWH    136          // 128 + 8 pad halfs

#define A_BYTES (32 * ROWH * 2)             // 8704
#define STAGE_BYTES (2 * A_BYTES)           // 17408
#define RED_OFF (STAGES * STAGE_BYTES)      // 69632
#define RED_BYTES (8 * 32 * 36 * 4)         // 36864
#define DYN_BYTES (RED_OFF + RED_BYTES)     // 106496

__device__ __half g_W16[2][L_DIM][G_DIM][W_DIM];   // transposed fp16 weights (64 MB)
__device__ __half g_x16[T_STEPS][B_DIM][W_DIM];
__device__ __half g_h16[L_DIM][B_DIM][W_DIM];      // layer-forward h (unmasked)
__device__ __half g_hm16[2][L_DIM][B_DIM][W_DIM];  // pre-masked recurrent h
__device__ float  g_c[L_DIM][B_DIM][W_DIM];
__device__ unsigned g_count = 0;
__device__ unsigned g_gen   = 0;

static __device__ __forceinline__ unsigned smem_u32(const void* p) {
    return (unsigned)__cvta_generic_to_shared(p);
}

__device__ __forceinline__ void gridBarrier() {
    __syncthreads();
    if (threadIdx.x == 0) {
        volatile unsigned* genp = &g_gen;
        unsigned my = *genp;
        __threadfence();
        unsigned arrived = atomicAdd(&g_count, 1);
        if (arrived == NB - 1) {
            atomicExch(&g_count, 0);
            __threadfence();
            *genp = my + 1;
        } else {
            while (*genp == my) { }
        }
        __threadfence();
    }
    __syncthreads();
}

__device__ __forceinline__ void cpa16(unsigned dst, const void* src) {
    asm volatile("cp.async.cg.shared.global [%0], [%1], 16;" :: "r"(dst), "l"(src));
}
#define CP_COMMIT() asm volatile("cp.async.commit_group;" ::: "memory")

#define LDSM4(r0, r1, r2, r3, addr) \
    asm volatile("ldmatrix.sync.aligned.m8n8.x4.shared.b16 {%0,%1,%2,%3}, [%4];" \
                 : "=r"(r0), "=r"(r1), "=r"(r2), "=r"(r3) : "r"(addr))

__device__ __forceinline__ void mma_f16(float& c0, float& c1, float& c2, float& c3,
                                        unsigned a0, unsigned a1, unsigned a2, unsigned a3,
                                        unsigned b0, unsigned b1) {
    asm volatile(
        "mma.sync.aligned.m16n8k16.row.col.f32.f16.f16.f32 "
        "{%0,%1,%2,%3}, {%4,%5,%6,%7}, {%8,%9}, {%0,%1,%2,%3};"
        : "+f"(c0), "+f"(c1), "+f"(c2), "+f"(c3)
        : "r"(a0), "r"(a1), "r"(a2), "r"(a3), "r"(b0), "r"(b1));
}

__device__ __forceinline__ float sigmoidf_(float v) { return 1.0f / (1.0f + expf(-v)); }

// ---------------- one-time converts ----------------
__global__ void convert_w_kernel(const float* __restrict__ Wx, const float* __restrict__ Wh) {
    __shared__ float tile[32][33];
    const int w = blockIdx.z >> 2, l = blockIdx.z & 3;
    const float* src = (w ? Wh : Wx) + (size_t)l * W_DIM * G_DIM;
    const int c0 = blockIdx.x * 32, k0 = blockIdx.y * 32;
    const int tx = threadIdx.x, ty = threadIdx.y;
    #pragma unroll
    for (int i = 0; i < 4; i++)
        tile[ty + 8 * i][tx] = src[(size_t)(k0 + ty + 8 * i) * G_DIM + c0 + tx];
    __syncthreads();
    __half* dst = &g_W16[w][l][0][0];
    #pragma unroll
    for (int i = 0; i < 4; i++)
        dst[(size_t)(c0 + ty + 8 * i) * W_DIM + k0 + tx] = __float2half(tile[tx][ty + 8 * i]);
}

__global__ void convert_x_kernel(const float* __restrict__ x) {
    __half* dst = &g_x16[0][0][0];
    int i = blockIdx.x * blockDim.x + threadIdx.x;
    #pragma unroll
    for (int r = 0; r < 8; ++r) {
        int idx = i + r * (gridDim.x * blockDim.x);
        if (idx < T_STEPS * B_DIM * W_DIM) dst[idx] = __float2half(x[idx]);
    }
}

#define RED_IDX(w, m, n) ((w) * 1152 + (m) * 36 + (n))

__global__ __launch_bounds__(NT) void lstm_mma_kernel(
    const void*  __restrict__ resets_raw,
    const float* __restrict__ c0,
    const float* __restrict__ h0,
    const float* __restrict__ bias,
    float* __restrict__ out)
{
    extern __shared__ __align__(16) char pool[];
    __shared__ float mask_next[B_DIM];
    __shared__ int s_rmode;

    const int tid  = threadIdx.x;
    const int cta  = blockIdx.x;
    const int lane = tid & 31;
    const int w    = tid >> 5;        // warp 0..7 -> k-slice w*16
    const int u0   = cta * 8;

    float* out_ys = out;
    float* out_cs = out + (size_t)T_STEPS * B_DIM * W_DIM;
    float* out_hs = out_cs + (size_t)L_DIM * B_DIM * W_DIM;

    if (tid == 0) {
        const unsigned char* rb = (const unsigned char*)resets_raw;
        int s1 = 0, s2 = 0, s3 = 0;
        for (int i = 0; i < T_STEPS * B_DIM; i += 4) { s1 += rb[i+1]; s2 += rb[i+2]; s3 += rb[i+3]; }
        s_rmode = (s1 > 0) ? 0 : ((s2 == 0 && s3 == 0) ? 1 : 2);
    }
    __syncthreads();
    const int rmode = s_rmode;

    const unsigned char* r8  = (const unsigned char*)resets_raw;
    const int*           r32 = (const int*)resets_raw;
    const float*         rf  = (const float*)resets_raw;
    #define KEEP(t, b) (rmode == 0 ? (r8[(t)*B_DIM+(b)] ? 0.0f : 1.0f) \
                      : rmode == 1 ? (r32[(t)*B_DIM+(b)] ? 0.0f : 1.0f) \
                                   : (rf[(t)*B_DIM+(b)] != 0.0f ? 0.0f : 1.0f))

    // ---- init state (pre-masked with keep[0]) ----
    for (int i = cta * NT + tid; i < L_DIM * B_DIM * W_DIM; i += NB * NT) {
        int b = (i >> 10) & 31;
        float k0f = KEEP(0, b);
        (&g_hm16[0][0][0][0])[i] = __float2half(k0f * h0[i]);
        (&g_c[0][0][0])[i]       = k0f * c0[i];
    }
    gridBarrier();

    const unsigned poolAddr = smem_u32(pool);
    float* red = (float*)(pool + RED_OFF);

    // ---- staging offset tables (o = tid + 256*i; m = o>>4, kq = o&15) ----
    unsigned wOff[2], wDst[2], actOff[2], actDst[2];
    #pragma unroll
    for (int i = 0; i < 2; ++i) {
        int o = tid + NT * i;
        int m = o >> 4, kq = o & 15;
        wOff[i]   = (unsigned)(((m >> 3) * W_DIM + u0 + (m & 7)) * W_DIM + kq * 8);
        wDst[i]   = (unsigned)((m * ROWH + kq * 8) * 2);
        actOff[i] = (unsigned)(m * W_DIM + kq * 8);
        actDst[i] = (unsigned)(A_BYTES + (m * ROWH + kq * 8) * 2);
    }

    #define STAGE_W(sidx, wb, kc) do { \
        const unsigned _b = poolAddr + (sidx) * STAGE_BYTES; \
        cpa16(_b + wDst[0], (wb) + wOff[0] + (kc)); \
        cpa16(_b + wDst[1], (wb) + wOff[1] + (kc)); \
    } while (0)
    #define STAGE_A(sidx, ab, kc) do { \
        const unsigned _b = poolAddr + (sidx) * STAGE_BYTES; \
        cpa16(_b + actDst[0], (ab) + actOff[0] + (kc)); \
        cpa16(_b + actDst[1], (ab) + actOff[1] + (kc)); \
    } while (0)

    // ---- ldmatrix fragment offsets (k-slice kb = w*16 halfs) ----
    const unsigned kByte = (unsigned)(w * 16 * 2);
    const int lrow8 = lane & 7;
    const unsigned aoff0 = (unsigned)(((lrow8 + ((lane >> 3) & 1) * 8) * ROWH
                                       + ((lane >> 4) & 1) * 8) * 2);
    const unsigned aoff1 = aoff0 + 16 * ROWH * 2;
    const unsigned boff0 = (unsigned)(((lrow8 + ((lane >> 4) & 1) * 8) * ROWH
                                       + ((lane >> 3) & 1) * 8) * 2);
    const unsigned boff1 = boff0 + 16 * ROWH * 2;

    const int row = lane >> 2;
    const int kc2 = (lane & 3) * 2;

    // ---- prime: phase-0 weight chunks 0..2 (3 separate groups) ----
    {
        const __half* wX0 = &g_W16[0][0][0][0];
        STAGE_W(0, wX0, 0);       CP_COMMIT();
        STAGE_W(1, wX0, KCH);     CP_COMMIT();
        STAGE_W(2, wX0, 2 * KCH); CP_COMMIT();
    }

    for (int t = 0; t < T_STEPS; ++t) {
        if (tid < B_DIM)
            mask_next[tid] = (t + 1 < T_STEPS) ? KEEP(t + 1, tid) : 1.0f;

        for (int l = 0; l < L_DIM; ++l) {
            const __half* wX = &g_W16[0][l][0][0];
            const __half* wH = &g_W16[1][l][0][0];
            const __half* ax = (l == 0) ? &g_x16[t][0][0] : &g_h16[l - 1][0][0];
            const __half* ah = &g_hm16[t & 1][l][0][0];

            // activations for chunks 0..2 (weights already in flight)
            STAGE_A(0, ax, 0);       CP_COMMIT();
            STAGE_A(1, ax, KCH);     CP_COMMIT();
            STAGE_A(2, ax, 2 * KCH); CP_COMMIT();

            float acc[2][4][4];
            #pragma unroll
            for (int mt = 0; mt < 2; ++mt)
                #pragma unroll
                for (int nt = 0; nt < 4; ++nt)
                    #pragma unroll
                    for (int q = 0; q < 4; ++q) acc[mt][nt][q] = 0.0f;

            for (int c = 0; c < NCH; ++c) {
                if (c <= NCH - 3)      asm volatile("cp.async.wait_group 2;" ::: "memory");
                else if (c == NCH - 2) asm volatile("cp.async.wait_group 1;" ::: "memory");
                else                   asm volatile("cp.async.wait_group 0;" ::: "memory");
                __syncthreads();

                if (c + 3 < NCH) {
                    const int cn = c + 3;
                    const __half* wb = (cn < 8) ? wX : wH;
                    const __half* ab = (cn < 8) ? ax : ah;
                    const unsigned kc = (unsigned)((cn & 7) * KCH);
                    const int s = cn & 3;
                    STAGE_W(s, wb, kc);
                    STAGE_A(s, ab, kc);
                    CP_COMMIT();
                }

                // ---- compute chunk c ----
                const unsigned asb = poolAddr + (c & 3) * STAGE_BYTES;
                const unsigned bsb = asb + A_BYTES;
                unsigned a0[4], a1[4], b0[4], b1[4];
                LDSM4(a0[0], a0[1], a0[2], a0[3], asb + aoff0 + kByte);
                LDSM4(a1[0], a1[1], a1[2], a1[3], asb + aoff1 + kByte);
                LDSM4(b0[0], b0[1], b0[2], b0[3], bsb + boff0 + kByte);
                LDSM4(b1[0], b1[1], b1[2], b1[3], bsb + boff1 + kByte);
                mma_f16(acc[0][0][0], acc[0][0][1], acc[0][0][2], acc[0][0][3],
                        a0[0], a0[1], a0[2], a0[3], b0[0], b0[1]);
                mma_f16(acc[0][1][0], acc[0][1][1], acc[0][1][2], acc[0][1][3],
                        a0[0], a0[1], a0[2], a0[3], b0[2], b0[3]);
                mma_f16(acc[0][2][0], acc[0][2][1], acc[0][2][2], acc[0][2][3],
                        a0[0], a0[1], a0[2], a0[3], b1[0], b1[1]);
                mma_f16(acc[0][3][0], acc[0][3][1], acc[0][3][2], acc[0][3][3],
                        a0[0], a0[1], a0[2], a0[3], b1[2], b1[3]);
                mma_f16(acc[1][0][0], acc[1][0][1], acc[1][0][2], acc[1][0][3],
                        a1[0], a1[1], a1[2], a1[3], b0[0], b0[1]);
                mma_f16(acc[1][1][0], acc[1][1][1], acc[1][1][2], acc[1][1][3],
                        a1[0], a1[1], a1[2], a1[3], b0[2], b0[3]);
                mma_f16(acc[1][2][0], acc[1][2][1], acc[1][2][2], acc[1][2][3],
                        a1[0], a1[1], a1[2], a1[3], b1[0], b1[1]);
                mma_f16(acc[1][3][0], acc[1][3][1], acc[1][3][2], acc[1][3][3],
                        a1[0], a1[1], a1[2], a1[3], b1[2], b1[3]);
            }

            // ---- cross-barrier prefetch: next phase's weight chunks 0..2 ----
            if (!(t == T_STEPS - 1 && l == L_DIM - 1)) {
                const int ln = (l + 1) & 3;
                const __half* wXn = &g_W16[0][ln][0][0];
                STAGE_W(0, wXn, 0);       CP_COMMIT();
                STAGE_W(1, wXn, KCH);     CP_COMMIT();
                STAGE_W(2, wXn, 2 * KCH); CP_COMMIT();
            }

            // ---- partial-sum exchange over k-slices ----
            #pragma unroll
            for (int mt = 0; mt < 2; ++mt)
                #pragma unroll
                for (int nt = 0; nt < 4; ++nt) {
                    float* p = &red[RED_IDX(w, mt * 16 + row, nt * 8 + kc2)];
                    *(float2*)p            = make_float2(acc[mt][nt][0], acc[mt][nt][1]);
                    *(float2*)(p + 8 * 36) = make_float2(acc[mt][nt][2], acc[mt][nt][3]);
                }
            __syncthreads();

            // ---- reduce + bias + LSTM pointwise ----
            {
                const int j = tid & 7;
                const int n = tid >> 3;
                const int u = u0 + j;
                float gate[4];
                #pragma unroll
                for (int g = 0; g < 4; ++g) {
                    float s = bias[l * G_DIM + g * W_DIM + u0 + j];
                    #pragma unroll
                    for (int ww = 0; ww < 8; ++ww) s += red[RED_IDX(ww, g * 8 + j, n)];
                    gate[g] = s;
                }
                float cOld = g_c[l][n][u];
                float cN = sigmoidf_(gate[1]) * cOld + sigmoidf_(gate[0]) * tanhf(gate[2]);
                float hN = sigmoidf_(gate[3]) * tanhf(cN);
                float keepN = mask_next[n];

                g_c[l][n][u]   = keepN * cN;
                g_h16[l][n][u] = __float2half(hN);
                g_hm16[(t + 1) & 1][l][n][u] = __float2half(keepN * hN);
                if (l == L_DIM - 1)
                    out_ys[((size_t)t * B_DIM + n) * W_DIM + u] = hN;
                if (t == T_STEPS - 1) {
                    out_cs[((size_t)l * B_DIM + n) * W_DIM + u] = cN;
                    out_hs[((size_t)l * B_DIM + n) * W_DIM + u] = hN;
                }
            }
            gridBarrier();
        }
    }
    #undef KEEP
}

extern "C" void kernel_launch(void* const* d_in, const int* in_sizes, int n_in,
                              void* d_out, int out_size) {
    const float* x      = (const float*)d_in[0];
    const void*  resets = (const void*) d_in[1];
    const float* c0     = (const float*)d_in[2];
    const float* h0     = (const float*)d_in[3];
    const float* Wx     = (const float*)d_in[4];
    const float* Wh     = (const float*)d_in[5];
    const float* b      = (const float*)d_in[6];
    (void)in_sizes; (void)n_in; (void)out_size;

    static int configured = 0;
    if (!configured) {
        cudaFuncSetAttribute(lstm_mma_kernel, cudaFuncAttributeMaxDynamicSharedMemorySize, DYN_BYTES);
        configured = 1;
    }

    convert_w_kernel<<<dim3(G_DIM / 32, W_DIM / 32, 8), dim3(32, 8)>>>(Wx, Wh);
    convert_x_kernel<<<1024, 256>>>(x);
    lstm_mma_kernel<<<NB, NT, DYN_BYTES>>>(resets, c0, h0, b, (float*)d_out);
}

// round 9
// speedup vs baseline: 2.1988x; 1.7665x over previous
#include <cuda_runtime.h>
#include <cuda_fp16.h>
#include <cstdint>

#define T_STEPS 64
#define B_DIM   32
#define W_DIM   1024
#define L_DIM   4
#define G_DIM   4096
#define NB      128
#define NT      256
#define KCH     128          // k halfs per chunk
#define NCH     16
#define NPHASE  (T_STEPS + L_DIM - 1)   // 67
#define ROWH    136          // 128 + 8 pad halfs

#define W_ST_BYTES (128 * ROWH * 2)         // 34816
#define A_OFF      W_ST_BYTES
#define STAGE_BYTES (W_ST_BYTES + 32 * ROWH * 2)   // 43520
#define RED_OFF    (4 * STAGE_BYTES)        // 174080
#define RED_BYTES  (2 * 128 * 36 * 4)       // 36864
#define DYN_BYTES  (RED_OFF + RED_BYTES)    // 210944

__device__ __half g_W16[2][L_DIM][G_DIM][W_DIM];   // transposed fp16 weights (64 MB)
__device__ __half g_x16[T_STEPS][B_DIM][W_DIM];
__device__ __half g_h16[2][L_DIM][B_DIM][W_DIM];   // by phase parity, unmasked
__device__ __half g_hm16[2][L_DIM][B_DIM][W_DIM];  // by phase parity, pre-masked
__device__ float  g_c[L_DIM][B_DIM][W_DIM];        // CTA-local, pre-masked
__device__ unsigned g_count = 0;
__device__ unsigned g_gen   = 0;

static __device__ __forceinline__ unsigned smem_u32(const void* p) {
    return (unsigned)__cvta_generic_to_shared(p);
}

__device__ __forceinline__ void gridBarrier() {
    __syncthreads();
    if (threadIdx.x == 0) {
        volatile unsigned* genp = &g_gen;
        unsigned my = *genp;
        __threadfence();
        unsigned arrived = atomicAdd(&g_count, 1);
        if (arrived == NB - 1) {
            atomicExch(&g_count, 0);
            __threadfence();
            *genp = my + 1;
        } else {
            while (*genp == my) { }
        }
        __threadfence();
    }
    __syncthreads();
}

__device__ __forceinline__ void cpa16(unsigned dst, const void* src) {
    asm volatile("cp.async.cg.shared.global [%0], [%1], 16;" :: "r"(dst), "l"(src));
}
#define CP_COMMIT() asm volatile("cp.async.commit_group;" ::: "memory")

#define LDSM4(r0, r1, r2, r3, addr) \
    asm volatile("ldmatrix.sync.aligned.m8n8.x4.shared.b16 {%0,%1,%2,%3}, [%4];" \
                 : "=r"(r0), "=r"(r1), "=r"(r2), "=r"(r3) : "r"(addr))

__device__ __forceinline__ void mma_f16(float& c0, float& c1, float& c2, float& c3,
                                        unsigned a0, unsigned a1, unsigned a2, unsigned a3,
                                        unsigned b0, unsigned b1) {
    asm volatile(
        "mma.sync.aligned.m16n8k16.row.col.f32.f16.f16.f32 "
        "{%0,%1,%2,%3}, {%4,%5,%6,%7}, {%8,%9}, {%0,%1,%2,%3};"
        : "+f"(c0), "+f"(c1), "+f"(c2), "+f"(c3)
        : "r"(a0), "r"(a1), "r"(a2), "r"(a3), "r"(b0), "r"(b1));
}

__device__ __forceinline__ float sigmoidf_(float v) { return 1.0f / (1.0f + expf(-v)); }

// ---------------- one-time converts ----------------
__global__ void convert_w_kernel(const float* __restrict__ Wx, const float* __restrict__ Wh) {
    __shared__ float tile[32][33];
    const int w = blockIdx.z >> 2, l = blockIdx.z & 3;
    const float* src = (w ? Wh : Wx) + (size_t)l * W_DIM * G_DIM;
    const int c0 = blockIdx.x * 32, k0 = blockIdx.y * 32;
    const int tx = threadIdx.x, ty = threadIdx.y;
    #pragma unroll
    for (int i = 0; i < 4; i++)
        tile[ty + 8 * i][tx] = src[(size_t)(k0 + ty + 8 * i) * G_DIM + c0 + tx];
    __syncthreads();
    __half* dst = &g_W16[w][l][0][0];
    #pragma unroll
    for (int i = 0; i < 4; i++)
        dst[(size_t)(c0 + ty + 8 * i) * W_DIM + k0 + tx] = __float2half(tile[tx][ty + 8 * i]);
}

__global__ void convert_x_kernel(const float* __restrict__ x) {
    __half* dst = &g_x16[0][0][0];
    int i = blockIdx.x * blockDim.x + threadIdx.x;
    #pragma unroll
    for (int r = 0; r < 8; ++r) {
        int idx = i + r * (gridDim.x * blockDim.x);
        if (idx < T_STEPS * B_DIM * W_DIM) dst[idx] = __float2half(x[idx]);
    }
}

__global__ __launch_bounds__(NT) void lstm_mma_kernel(
    const void*  __restrict__ resets_raw,
    const float* __restrict__ c0,
    const float* __restrict__ h0,
    const float* __restrict__ bias,
    float* __restrict__ out)
{
    extern __shared__ __align__(16) char pool[];
    __shared__ float mask_next[B_DIM];
    __shared__ int s_rmode;

    const int tid  = threadIdx.x;
    const int cta  = blockIdx.x;
    const int lane = tid & 31;
    const int w    = tid >> 5;
    const int grp  = cta >> 5;        // layer this CTA group owns
    const int lcta = cta & 31;
    const int u0   = lcta * 32;       // 32 units per CTA
    const int ms   = w >> 1;          // M-slice 0..3 (32 rows)
    const int ks   = w & 1;           // K-slice 0..1 (64 halfs)
    const int mbase = ms * 32;

    float* out_ys = out;
    float* out_cs = out + (size_t)T_STEPS * B_DIM * W_DIM;
    float* out_hs = out_cs + (size_t)L_DIM * B_DIM * W_DIM;

    if (tid == 0) {
        const unsigned char* rb = (const unsigned char*)resets_raw;
        int s1 = 0, s2 = 0, s3 = 0;
        for (int i = 0; i < T_STEPS * B_DIM; i += 4) { s1 += rb[i+1]; s2 += rb[i+2]; s3 += rb[i+3]; }
        s_rmode = (s1 > 0) ? 0 : ((s2 == 0 && s3 == 0) ? 1 : 2);
    }
    __syncthreads();
    const int rmode = s_rmode;

    const unsigned char* r8  = (const unsigned char*)resets_raw;
    const int*           r32 = (const int*)resets_raw;
    const float*         rf  = (const float*)resets_raw;
    #define KEEP(t, b) (rmode == 0 ? (r8[(t)*B_DIM+(b)] ? 0.0f : 1.0f) \
                      : rmode == 1 ? (r32[(t)*B_DIM+(b)] ? 0.0f : 1.0f) \
                                   : (rf[(t)*B_DIM+(b)] != 0.0f ? 0.0f : 1.0f))

    // ---- init state: pre-masked with keep[0]; both hm parities ----
    for (int i = cta * NT + tid; i < L_DIM * B_DIM * W_DIM; i += NB * NT) {
        int b = (i >> 10) & 31;
        float k0f = KEEP(0, b);
        __half hv = __float2half(k0f * h0[i]);
        (&g_hm16[0][0][0][0])[i] = hv;
        (&g_hm16[1][0][0][0])[i] = hv;
        (&g_c[0][0][0])[i]       = k0f * c0[i];
    }
    gridBarrier();

    const unsigned poolAddr = smem_u32(pool);
    float* red = (float*)(pool + RED_OFF);
    #define RED_IDX(kk, m, n) ((kk) * 4608 + (m) * 36 + (n))

    // ---- staging offset tables ----
    unsigned wOff[8], wDst[8], aOff[2], aDst[2];
    #pragma unroll
    for (int i = 0; i < 8; ++i) {
        int o = tid + NT * i;              // 0..2047
        int m = o >> 4, kq = o & 15;       // row 0..127, 8-half quantum
        wOff[i] = (unsigned)(((m >> 5) * W_DIM + u0 + (m & 31)) * W_DIM + kq * 8);
        wDst[i] = (unsigned)((m * ROWH + kq * 8) * 2);
    }
    #pragma unroll
    for (int i = 0; i < 2; ++i) {
        int o = tid + NT * i;              // 0..511
        int n = o >> 4, kq = o & 15;
        aOff[i] = (unsigned)(n * W_DIM + kq * 8);
        aDst[i] = (unsigned)(A_OFF + (n * ROWH + kq * 8) * 2);
    }

    #define STAGE(sidx, wb, ab, kc) do { \
        const unsigned _b = poolAddr + (sidx) * STAGE_BYTES; \
        _Pragma("unroll") \
        for (int _i = 0; _i < 8; ++_i) cpa16(_b + wDst[_i], (wb) + wOff[_i] + (kc)); \
        cpa16(_b + aDst[0], (ab) + aOff[0] + (kc)); \
        cpa16(_b + aDst[1], (ab) + aOff[1] + (kc)); \
    } while (0)

    // ---- ldmatrix fragment offsets ----
    const int lrow8 = lane & 7;
    unsigned aRow[2], bRow[2];
    #pragma unroll
    for (int mt = 0; mt < 2; ++mt)
        aRow[mt] = (unsigned)((mbase + mt * 16 + lrow8 + ((lane >> 3) & 1) * 8) * ROWH * 2);
    #pragma unroll
    for (int nt2 = 0; nt2 < 2; ++nt2)
        bRow[nt2] = (unsigned)((nt2 * 16 + lrow8 + ((lane >> 4) & 1) * 8) * ROWH * 2);
    const unsigned aKadj = (unsigned)(((lane >> 4) & 1) * 8 * 2);
    const unsigned bKadj = (unsigned)(((lane >> 3) & 1) * 8 * 2);
    const unsigned kBase = (unsigned)(ks * 64 * 2);

    const int row = lane >> 2;
    const int kc2 = (lane & 3) * 2;

    for (int d = 0; d < NPHASE; ++d) {
        const int t = d - grp;
        const bool active = (t >= 0 && t < T_STEPS);

        if (active) {
            if (tid < B_DIM)
                mask_next[tid] = (t + 1 < T_STEPS) ? KEEP(t + 1, tid) : 1.0f;

            const int pprev = (d + 1) & 1;   // == (d-1)&1
            const __half* wX = &g_W16[0][grp][0][0];
            const __half* wH = &g_W16[1][grp][0][0];
            const __half* ax = (grp == 0) ? &g_x16[t][0][0] : &g_h16[pprev][grp - 1][0][0];
            const __half* ah = &g_hm16[pprev][grp][0][0];

            // prologue: stage chunks 0..2
            STAGE(0, wX, ax, 0);       CP_COMMIT();
            STAGE(1, wX, ax, KCH);     CP_COMMIT();
            STAGE(2, wX, ax, 2 * KCH); CP_COMMIT();

            float acc[2][4][4];
            #pragma unroll
            for (int mt = 0; mt < 2; ++mt)
                #pragma unroll
                for (int nt = 0; nt < 4; ++nt)
                    #pragma unroll
                    for (int q = 0; q < 4; ++q) acc[mt][nt][q] = 0.0f;

            for (int c = 0; c < NCH; ++c) {
                if (c <= NCH - 3)      asm volatile("cp.async.wait_group 2;" ::: "memory");
                else if (c == NCH - 2) asm volatile("cp.async.wait_group 1;" ::: "memory");
                else                   asm volatile("cp.async.wait_group 0;" ::: "memory");
                __syncthreads();

                if (c + 3 < NCH) {
                    const int cn = c + 3;
                    const __half* wb = (cn < 8) ? wX : wH;
                    const __half* ab = (cn < 8) ? ax : ah;
                    STAGE(cn & 3, wb, ab, (unsigned)((cn & 7) * KCH));
                    CP_COMMIT();
                }

                const unsigned asb = poolAddr + (c & 3) * STAGE_BYTES;
                const unsigned bsb = asb + A_OFF;
                #pragma unroll
                for (int s = 0; s < 4; ++s) {
                    const unsigned kOff = kBase + (unsigned)(s * 16 * 2);
                    unsigned a0[4], a1[4], b0[4], b1[4];
                    LDSM4(a0[0], a0[1], a0[2], a0[3], asb + aRow[0] + kOff + aKadj);
                    LDSM4(a1[0], a1[1], a1[2], a1[3], asb + aRow[1] + kOff + aKadj);
                    LDSM4(b0[0], b0[1], b0[2], b0[3], bsb + bRow[0] + kOff + bKadj);
                    LDSM4(b1[0], b1[1], b1[2], b1[3], bsb + bRow[1] + kOff + bKadj);
                    mma_f16(acc[0][0][0], acc[0][0][1], acc[0][0][2], acc[0][0][3],
                            a0[0], a0[1], a0[2], a0[3], b0[0], b0[1]);
                    mma_f16(acc[0][1][0], acc[0][1][1], acc[0][1][2], acc[0][1][3],
                            a0[0], a0[1], a0[2], a0[3], b0[2], b0[3]);
                    mma_f16(acc[0][2][0], acc[0][2][1], acc[0][2][2], acc[0][2][3],
                            a0[0], a0[1], a0[2], a0[3], b1[0], b1[1]);
                    mma_f16(acc[0][3][0], acc[0][3][1], acc[0][3][2], acc[0][3][3],
                            a0[0], a0[1], a0[2], a0[3], b1[2], b1[3]);
                    mma_f16(acc[1][0][0], acc[1][0][1], acc[1][0][2], acc[1][0][3],
                            a1[0], a1[1], a1[2], a1[3], b0[0], b0[1]);
                    mma_f16(acc[1][1][0], acc[1][1][1], acc[1][1][2], acc[1][1][3],
                            a1[0], a1[1], a1[2], a1[3], b0[2], b0[3]);
                    mma_f16(acc[1][2][0], acc[1][2][1], acc[1][2][2], acc[1][2][3],
                            a1[0], a1[1], a1[2], a1[3], b1[0], b1[1]);
                    mma_f16(acc[1][3][0], acc[1][3][1], acc[1][3][2], acc[1][3][3],
                            a1[0], a1[1], a1[2], a1[3], b1[2], b1[3]);
                }
            }

            // ---- k-slice partial exchange ----
            #pragma unroll
            for (int mt = 0; mt < 2; ++mt)
                #pragma unroll
                for (int nt = 0; nt < 4; ++nt) {
                    const int m_r = mbase + mt * 16 + row;
                    const int n0  = nt * 8 + kc2;
                    *(float2*)&red[RED_IDX(ks, m_r, n0)] =
                        make_float2(acc[mt][nt][0], acc[mt][nt][1]);
                    *(float2*)&red[RED_IDX(ks, m_r + 8, n0)] =
                        make_float2(acc[mt][nt][2], acc[mt][nt][3]);
                }
            __syncthreads();

            // ---- reduce + bias + LSTM pointwise (4 batches per thread) ----
            {
                const int j  = tid & 31;       // unit within CTA
                const int nq = tid >> 5;       // 0..7
                const int u  = u0 + j;
                #pragma unroll
                for (int bq = 0; bq < 4; ++bq) {
                    const int n = nq * 4 + bq;
                    float gate[4];
                    #pragma unroll
                    for (int g = 0; g < 4; ++g) {
                        const int m = g * 32 + j;
                        gate[g] = red[RED_IDX(0, m, n)] + red[RED_IDX(1, m, n)]
                                + bias[grp * G_DIM + g * W_DIM + u];
                    }
                    float cOld = g_c[grp][n][u];
                    float cN = sigmoidf_(gate[1]) * cOld + sigmoidf_(gate[0]) * tanhf(gate[2]);
                    float hN = sigmoidf_(gate[3]) * tanhf(cN);
                    float keepN = mask_next[n];

                    g_c[grp][n][u] = keepN * cN;
                    g_h16[d & 1][grp][n][u]  = __float2half(hN);
                    g_hm16[d & 1][grp][n][u] = __float2half(keepN * hN);
                    if (grp == L_DIM - 1)
                        out_ys[((size_t)t * B_DIM + n) * W_DIM + u] = hN;
                    if (t == T_STEPS - 1) {
                        out_cs[((size_t)grp * B_DIM + n) * W_DIM + u] = cN;
                        out_hs[((size_t)grp * B_DIM + n) * W_DIM + u] = hN;
                    }
                }
            }
        }
        gridBarrier();
    }
    #undef KEEP
    #undef RED_IDX
}

extern "C" void kernel_launch(void* const* d_in, const int* in_sizes, int n_in,
                              void* d_out, int out_size) {
    const float* x      = (const float*)d_in[0];
    const void*  resets = (const void*) d_in[1];
    const float* c0     = (const float*)d_in[2];
    const float* h0     = (const float*)d_in[3];
    const float* Wx     = (const float*)d_in[4];
    const float* Wh     = (const float*)d_in[5];
    const float* b      = (const float*)d_in[6];
    (void)in_sizes; (void)n_in; (void)out_size;

    static int configured = 0;
    if (!configured) {
        cudaFuncSetAttribute(lstm_mma_kernel, cudaFuncAttributeMaxDynamicSharedMemorySize, DYN_BYTES);
        configured = 1;
    }

    convert_w_kernel<<<dim3(G_DIM / 32, W_DIM / 32, 8), dim3(32, 8)>>>(Wx, Wh);
    convert_x_kernel<<<1024, 256>>>(x);
    lstm_mma_kernel<<<NB, NT, DYN_BYTES>>>(resets, c0, h0, b, (float*)d_out);
}

// round 10
// speedup vs baseline: 3.2327x; 1.4702x over previous
#include <cuda_runtime.h>
#include <cuda_fp16.h>
#include <cstdint>

#define T_STEPS 64
#define B_DIM   32
#define W_DIM   1024
#define L_DIM   4
#define G_DIM   4096
#define NB      128
#define NT      512
#define KCH     128
#define NCH     16
#define NPHASE  (T_STEPS + L_DIM - 1)   // 67
#define ROWH    136

#define B_ST_BYTES (32 * ROWH * 2)          // 8704 per stage
#define RED_OFF    (4 * B_ST_BYTES)         // 34816
#define RED_BYTES  (4 * 128 * 36 * 4)       // 73728
#define DYN_BYTES  (RED_OFF + RED_BYTES)    // 108544

// weights in MMA-fragment order: [z=(wsel*4+l)*32+lcta][mtile 8][kstep 64][lane 32] x uint4
__device__ uint4  g_Wfrag[256 * 8 * 64 * 32];      // 67 MB
__device__ __half g_x16[T_STEPS][B_DIM][W_DIM];
__device__ __half g_h16[2][L_DIM][B_DIM][W_DIM];   // by phase parity, unmasked
__device__ __half g_hm16[2][L_DIM][B_DIM][W_DIM];  // by phase parity, pre-masked
__device__ float  g_c[L_DIM][B_DIM][W_DIM];
__device__ unsigned g_count = 0;
__device__ unsigned g_gen   = 0;

static __device__ __forceinline__ unsigned smem_u32(const void* p) {
    return (unsigned)__cvta_generic_to_shared(p);
}

__device__ __forceinline__ void gridBarrier() {
    __syncthreads();
    if (threadIdx.x == 0) {
        volatile unsigned* genp = &g_gen;
        unsigned my = *genp;
        __threadfence();
        unsigned arrived = atomicAdd(&g_count, 1);
        if (arrived == NB - 1) {
            atomicExch(&g_count, 0);
            __threadfence();
            *genp = my + 1;
        } else {
            while (*genp == my) { }
        }
        __threadfence();
    }
    __syncthreads();
}

__device__ __forceinline__ void cpa16(unsigned dst, const void* src) {
    asm volatile("cp.async.cg.shared.global [%0], [%1], 16;" :: "r"(dst), "l"(src));
}
#define CP_COMMIT() asm volatile("cp.async.commit_group;" ::: "memory")

#define LDSM4(r0, r1, r2, r3, addr) \
    asm volatile("ldmatrix.sync.aligned.m8n8.x4.shared.b16 {%0,%1,%2,%3}, [%4];" \
                 : "=r"(r0), "=r"(r1), "=r"(r2), "=r"(r3) : "r"(addr))

__device__ __forceinline__ void mma_f16(float& c0, float& c1, float& c2, float& c3,
                                        unsigned a0, unsigned a1, unsigned a2, unsigned a3,
                                        unsigned b0, unsigned b1) {
    asm volatile(
        "mma.sync.aligned.m16n8k16.row.col.f32.f16.f16.f32 "
        "{%0,%1,%2,%3}, {%4,%5,%6,%7}, {%8,%9}, {%0,%1,%2,%3};"
        : "+f"(c0), "+f"(c1), "+f"(c2), "+f"(c3)
        : "r"(a0), "r"(a1), "r"(a2), "r"(a3), "r"(b0), "r"(b1));
}

__device__ __forceinline__ float sigmoidf_(float v) { return 1.0f / (1.0f + expf(-v)); }

// ---------------- one-time converts ----------------
// Pre-swizzle weights into per-lane fragment quads {a0,a1,a2,a3} (8 halfs = 16 B).
__global__ void convert_wfrag_kernel(const float* __restrict__ Wx, const float* __restrict__ Wh) {
    __shared__ float sm[128][17];
    const int kg    = blockIdx.x;      // 0..7   (128 k each)
    const int mtile = blockIdx.y;      // 0..7
    const int z     = blockIdx.z;      // 0..255 = (wsel*4+l)*32 + lcta
    const int wsel  = z >> 7;
    const int l     = (z >> 5) & 3;
    const int lcta  = z & 31;
    const float* src = (wsel ? Wh : Wx) + (size_t)l * W_DIM * G_DIM;
    const int col_base = (mtile >> 1) * W_DIM + lcta * 32 + (mtile & 1) * 16;
    const int kbase = kg * 128;
    const int tid = threadIdx.x;

    const int cc = tid & 15, krow = tid >> 4;
    #pragma unroll
    for (int rep = 0; rep < 8; ++rep) {
        int k = krow + rep * 16;
        sm[k][cc] = src[(size_t)(kbase + k) * G_DIM + col_base + cc];
    }
    __syncthreads();

    const int ksl = tid >> 5, lane = tid & 31;
    const int r = lane >> 2, c2 = (lane & 3) * 2;
    const int kl = ksl * 16 + c2;
    unsigned short h[8];
    h[0] = __half_as_ushort(__float2half(sm[kl    ][r]));
    h[1] = __half_as_ushort(__float2half(sm[kl + 1][r]));
    h[2] = __half_as_ushort(__float2half(sm[kl    ][r + 8]));
    h[3] = __half_as_ushort(__float2half(sm[kl + 1][r + 8]));
    h[4] = __half_as_ushort(__float2half(sm[kl + 8][r]));
    h[5] = __half_as_ushort(__float2half(sm[kl + 9][r]));
    h[6] = __half_as_ushort(__float2half(sm[kl + 8][r + 8]));
    h[7] = __half_as_ushort(__float2half(sm[kl + 9][r + 8]));
    uint4 q;
    q.x = (unsigned)h[0] | ((unsigned)h[1] << 16);
    q.y = (unsigned)h[2] | ((unsigned)h[3] << 16);
    q.z = (unsigned)h[4] | ((unsigned)h[5] << 16);
    q.w = (unsigned)h[6] | ((unsigned)h[7] << 16);
    g_Wfrag[(((size_t)z * 8 + mtile) * 64 + kg * 8 + ksl) * 32 + lane] = q;
}

__global__ void convert_x_kernel(const float* __restrict__ x) {
    __half* dst = &g_x16[0][0][0];
    int i = blockIdx.x * blockDim.x + threadIdx.x;
    #pragma unroll
    for (int r = 0; r < 8; ++r) {
        int idx = i + r * (gridDim.x * blockDim.x);
        if (idx < T_STEPS * B_DIM * W_DIM) dst[idx] = __float2half(x[idx]);
    }
}

__global__ __launch_bounds__(NT) void lstm_mma_kernel(
    const void*  __restrict__ resets_raw,
    const float* __restrict__ c0,
    const float* __restrict__ h0,
    const float* __restrict__ bias,
    float* __restrict__ out)
{
    extern __shared__ __align__(16) char pool[];
    __shared__ float mask_next[B_DIM];
    __shared__ int s_rmode;

    const int tid  = threadIdx.x;
    const int cta  = blockIdx.x;
    const int lane = tid & 31;
    const int w    = tid >> 5;        // 0..15
    const int grp  = cta >> 5;        // layer owned
    const int lcta = cta & 31;
    const int u0   = lcta * 32;
    const int ms   = w >> 2;          // M-slice 0..3 (32 rows)
    const int ks   = w & 3;           // K-slice 0..3 (32 halfs)

    float* out_ys = out;
    float* out_cs = out + (size_t)T_STEPS * B_DIM * W_DIM;
    float* out_hs = out_cs + (size_t)L_DIM * B_DIM * W_DIM;

    if (tid == 0) {
        const unsigned char* rb = (const unsigned char*)resets_raw;
        int s1 = 0, s2 = 0, s3 = 0;
        for (int i = 0; i < T_STEPS * B_DIM; i += 4) { s1 += rb[i+1]; s2 += rb[i+2]; s3 += rb[i+3]; }
        s_rmode = (s1 > 0) ? 0 : ((s2 == 0 && s3 == 0) ? 1 : 2);
    }
    __syncthreads();
    const int rmode = s_rmode;

    const unsigned char* r8  = (const unsigned char*)resets_raw;
    const int*           r32 = (const int*)resets_raw;
    const float*         rf  = (const float*)resets_raw;
    #define KEEP(t, b) (rmode == 0 ? (r8[(t)*B_DIM+(b)] ? 0.0f : 1.0f) \
                      : rmode == 1 ? (r32[(t)*B_DIM+(b)] ? 0.0f : 1.0f) \
                                   : (rf[(t)*B_DIM+(b)] != 0.0f ? 0.0f : 1.0f))

    // ---- init state: pre-masked with keep[0]; both hm parities ----
    for (int i = cta * NT + tid; i < L_DIM * B_DIM * W_DIM; i += NB * NT) {
        int b = (i >> 10) & 31;
        float k0f = KEEP(0, b);
        __half hv = __float2half(k0f * h0[i]);
        (&g_hm16[0][0][0][0])[i] = hv;
        (&g_hm16[1][0][0][0])[i] = hv;
        (&g_c[0][0][0])[i]       = k0f * c0[i];
    }
    gridBarrier();

    const unsigned poolAddr = smem_u32(pool);
    float* red = (float*)(pool + RED_OFF);
    #define RED_IDX(kk, m, n) (((kk) * 128 + (m)) * 36 + (n))

    // ---- weight fragment bases ----
    const uint4* wbX = g_Wfrag + (((size_t)(0 * 4 + grp) * 32 + lcta) * 8) * 64 * 32;
    const uint4* wbH = g_Wfrag + (((size_t)(1 * 4 + grp) * 32 + lcta) * 8) * 64 * 32;
    // fidx[mt][s] relative index (add (c&7)*256 for chunk)
    unsigned fidx[2][2];
    #pragma unroll
    for (int mt = 0; mt < 2; ++mt)
        #pragma unroll
        for (int s = 0; s < 2; ++s)
            fidx[mt][s] = (unsigned)((((ms * 2 + mt) * 64) + ks * 2 + s) * 32 + lane);

    // ---- B (activation) staging: one cpa16 per thread per chunk ----
    const int bn  = tid >> 4;          // 0..31 batch
    const int bkq = tid & 15;
    const unsigned bDst = (unsigned)((bn * ROWH + bkq * 8) * 2);
    const unsigned bSrc = (unsigned)(bn * W_DIM + bkq * 8);

    // ---- B ldmatrix offsets ----
    const int lrow8 = lane & 7;
    unsigned bRow[2];
    #pragma unroll
    for (int nt2 = 0; nt2 < 2; ++nt2)
        bRow[nt2] = (unsigned)((nt2 * 16 + lrow8 + ((lane >> 4) & 1) * 8) * ROWH * 2);
    const unsigned bKadj = (unsigned)(((lane >> 3) & 1) * 8 * 2);
    const unsigned kBase = (unsigned)(ks * 32 * 2);     // ks slice byte offset in chunk

    const int row = lane >> 2;
    const int kc2 = (lane & 3) * 2;

    for (int d = 0; d < NPHASE; ++d) {
        const int t = d - grp;
        const bool active = (t >= 0 && t < T_STEPS);

        if (active) {
            if (tid < B_DIM)
                mask_next[tid] = (t + 1 < T_STEPS) ? KEEP(t + 1, tid) : 1.0f;

            const int pprev = (d + 1) & 1;
            const __half* ax = (grp == 0) ? &g_x16[t][0][0] : &g_h16[pprev][grp - 1][0][0];
            const __half* ah = &g_hm16[pprev][grp][0][0];

            // prologue: stage B chunks 0..2
            cpa16(poolAddr + 0 * B_ST_BYTES + bDst, ax + bSrc);           CP_COMMIT();
            cpa16(poolAddr + 1 * B_ST_BYTES + bDst, ax + bSrc + KCH);     CP_COMMIT();
            cpa16(poolAddr + 2 * B_ST_BYTES + bDst, ax + bSrc + 2 * KCH); CP_COMMIT();

            // prologue: A fragments chunk 0
            uint4 afrag[2][4];
            #pragma unroll
            for (int f = 0; f < 4; ++f)
                afrag[0][f] = wbX[fidx[f >> 1][f & 1]];

            float acc[2][4][4];
            #pragma unroll
            for (int mt = 0; mt < 2; ++mt)
                #pragma unroll
                for (int nt = 0; nt < 4; ++nt)
                    #pragma unroll
                    for (int q = 0; q < 4; ++q) acc[mt][nt][q] = 0.0f;

            for (int c = 0; c < NCH; ++c) {
                // prefetch A fragments chunk c+1 (regs; no smem hazard)
                if (c + 1 < NCH) {
                    const int cn = c + 1;
                    const uint4* wb = (cn < 8) ? wbX : wbH;
                    const unsigned co = (unsigned)((cn & 7) * 256);
                    #pragma unroll
                    for (int f = 0; f < 4; ++f)
                        afrag[cn & 1][f] = wb[co + fidx[f >> 1][f & 1]];
                }

                if (c <= NCH - 3)      asm volatile("cp.async.wait_group 2;" ::: "memory");
                else if (c == NCH - 2) asm volatile("cp.async.wait_group 1;" ::: "memory");
                else                   asm volatile("cp.async.wait_group 0;" ::: "memory");
                __syncthreads();

                if (c + 3 < NCH) {
                    const int cn = c + 3;
                    const __half* ab = (cn < 8) ? ax : ah;
                    cpa16(poolAddr + (cn & 3) * B_ST_BYTES + bDst,
                          ab + bSrc + (cn & 7) * KCH);
                    CP_COMMIT();
                }

                // ---- compute chunk c ----
                const unsigned bsb = poolAddr + (c & 3) * B_ST_BYTES;
                #pragma unroll
                for (int s = 0; s < 2; ++s) {
                    const unsigned kOff = kBase + (unsigned)(s * 16 * 2);
                    unsigned b0[4], b1[4];
                    LDSM4(b0[0], b0[1], b0[2], b0[3], bsb + bRow[0] + kOff + bKadj);
                    LDSM4(b1[0], b1[1], b1[2], b1[3], bsb + bRow[1] + kOff + bKadj);
                    #pragma unroll
                    for (int mt = 0; mt < 2; ++mt) {
                        const uint4 q = afrag[c & 1][mt * 2 + s];
                        mma_f16(acc[mt][0][0], acc[mt][0][1], acc[mt][0][2], acc[mt][0][3],
                                q.x, q.y, q.z, q.w, b0[0], b0[1]);
                        mma_f16(acc[mt][1][0], acc[mt][1][1], acc[mt][1][2], acc[mt][1][3],
                                q.x, q.y, q.z, q.w, b0[2], b0[3]);
                        mma_f16(acc[mt][2][0], acc[mt][2][1], acc[mt][2][2], acc[mt][2][3],
                                q.x, q.y, q.z, q.w, b1[0], b1[1]);
                        mma_f16(acc[mt][3][0], acc[mt][3][1], acc[mt][3][2], acc[mt][3][3],
                                q.x, q.y, q.z, q.w, b1[2], b1[3]);
                    }
                }
            }

            // ---- k-slice partial exchange ----
            #pragma unroll
            for (int mt = 0; mt < 2; ++mt)
                #pragma unroll
                for (int nt = 0; nt < 4; ++nt) {
                    const int m_r = ms * 32 + mt * 16 + row;
                    const int n0  = nt * 8 + kc2;
                    *(float2*)&red[RED_IDX(ks, m_r, n0)] =
                        make_float2(acc[mt][nt][0], acc[mt][nt][1]);
                    *(float2*)&red[RED_IDX(ks, m_r + 8, n0)] =
                        make_float2(acc[mt][nt][2], acc[mt][nt][3]);
                }
            __syncthreads();

            // ---- reduce + bias + LSTM pointwise (2 cells per thread) ----
            {
                const int u  = tid & 31;
                const int np = tid >> 5;       // 0..15
                const int ug = u0 + u;
                #pragma unroll
                for (int e = 0; e < 2; ++e) {
                    const int n = np * 2 + e;
                    float gate[4];
                    #pragma unroll
                    for (int g = 0; g < 4; ++g) {
                        const int m = g * 32 + u;
                        gate[g] = red[RED_IDX(0, m, n)] + red[RED_IDX(1, m, n)]
                                + red[RED_IDX(2, m, n)] + red[RED_IDX(3, m, n)]
                                + bias[grp * G_DIM + g * W_DIM + ug];
                    }
                    float cOld = g_c[grp][n][ug];
                    float cN = sigmoidf_(gate[1]) * cOld + sigmoidf_(gate[0]) * tanhf(gate[2]);
                    float hN = sigmoidf_(gate[3]) * tanhf(cN);
                    float keepN = mask_next[n];

                    g_c[grp][n][ug] = keepN * cN;
                    g_h16[d & 1][grp][n][ug]  = __float2half(hN);
                    g_hm16[d & 1][grp][n][ug] = __float2half(keepN * hN);
                    if (grp == L_DIM - 1)
                        out_ys[((size_t)t * B_DIM + n) * W_DIM + ug] = hN;
                    if (t == T_STEPS - 1) {
                        out_cs[((size_t)grp * B_DIM + n) * W_DIM + ug] = cN;
                        out_hs[((size_t)grp * B_DIM + n) * W_DIM + ug] = hN;
                    }
                }
            }
        }
        gridBarrier();
    }
    #undef KEEP
    #undef RED_IDX
}

extern "C" void kernel_launch(void* const* d_in, const int* in_sizes, int n_in,
                              void* d_out, int out_size) {
    const float* x      = (const float*)d_in[0];
    const void*  resets = (const void*) d_in[1];
    const float* c0     = (const float*)d_in[2];
    const float* h0     = (const float*)d_in[3];
    const float* Wx     = (const float*)d_in[4];
    const float* Wh     = (const float*)d_in[5];
    const float* b      = (const float*)d_in[6];
    (void)in_sizes; (void)n_in; (void)out_size;

    static int configured = 0;
    if (!configured) {
        cudaFuncSetAttribute(lstm_mma_kernel, cudaFuncAttributeMaxDynamicSharedMemorySize, DYN_BYTES);
        configured = 1;
    }

    convert_wfrag_kernel<<<dim3(8, 8, 256), 256>>>(Wx, Wh);
    convert_x_kernel<<<1024, 256>>>(x);
    lstm_mma_kernel<<<NB, NT, DYN_BYTES>>>(resets, c0, h0, b, (float*)d_out);
}

// round 11
// speedup vs baseline: 3.5609x; 1.1015x over previous
#include <cuda_runtime.h>
#include <cuda_fp16.h>
#include <cstdint>

#define T_STEPS 64
#define B_DIM   32
#define W_DIM   1024
#define L_DIM   4
#define G_DIM   4096
#define NB      128
#define NT      512
#define KCH     128
#define NCH     16
#define ROWH    136

#define B_ST_BYTES (32 * ROWH * 2)          // 8704 per stage
#define RED_OFF    (4 * B_ST_BYTES)         // 34816
#define RED_BYTES  (4 * 128 * 36 * 4)       // 73728
#define DYN_BYTES  (RED_OFF + RED_BYTES)    // 108544

// weights in MMA-fragment order: [z=(wsel*4+l)*32+lcta][mtile 8][kstep 64][lane 32] x uint4
__device__ uint4  g_Wfrag[256 * 8 * 64 * 32];        // 67 MB
__device__ __half g_x16[T_STEPS][B_DIM][W_DIM];
__device__ __half g_hy[L_DIM][T_STEPS][B_DIM][W_DIM];     // unmasked h per (l,t)
__device__ __half g_hm[L_DIM][T_STEPS + 1][B_DIM][W_DIM]; // pre-masked recurrent, slot t
__device__ float  g_c[L_DIM][B_DIM][W_DIM];
__device__ unsigned g_done[L_DIM][T_STEPS];
__device__ unsigned g_count = 0;
__device__ unsigned g_gen   = 0;

static __device__ __forceinline__ unsigned smem_u32(const void* p) {
    return (unsigned)__cvta_generic_to_shared(p);
}

__device__ __forceinline__ void gridBarrier() {
    __syncthreads();
    if (threadIdx.x == 0) {
        volatile unsigned* genp = &g_gen;
        unsigned my = *genp;
        __threadfence();
        unsigned arrived = atomicAdd(&g_count, 1);
        if (arrived == NB - 1) {
            atomicExch(&g_count, 0);
            __threadfence();
            *genp = my + 1;
        } else {
            while (*genp == my) { }
        }
        __threadfence();
    }
    __syncthreads();
}

__device__ __forceinline__ void cpa16(unsigned dst, const void* src) {
    asm volatile("cp.async.cg.shared.global [%0], [%1], 16;" :: "r"(dst), "l"(src));
}
#define CP_COMMIT() asm volatile("cp.async.commit_group;" ::: "memory")

#define LDSM4(r0, r1, r2, r3, addr) \
    asm volatile("ldmatrix.sync.aligned.m8n8.x4.shared.b16 {%0,%1,%2,%3}, [%4];" \
                 : "=r"(r0), "=r"(r1), "=r"(r2), "=r"(r3) : "r"(addr))

__device__ __forceinline__ void mma_f16(float& c0, float& c1, float& c2, float& c3,
                                        unsigned a0, unsigned a1, unsigned a2, unsigned a3,
                                        unsigned b0, unsigned b1) {
    asm volatile(
        "mma.sync.aligned.m16n8k16.row.col.f32.f16.f16.f32 "
        "{%0,%1,%2,%3}, {%4,%5,%6,%7}, {%8,%9}, {%0,%1,%2,%3};"
        : "+f"(c0), "+f"(c1), "+f"(c2), "+f"(c3)
        : "r"(a0), "r"(a1), "r"(a2), "r"(a3), "r"(b0), "r"(b1));
}

__device__ __forceinline__ float sigmoidf_(float v) { return 1.0f / (1.0f + expf(-v)); }

// ---------------- one-time converts ----------------
__global__ void convert_wfrag_kernel(const float* __restrict__ Wx, const float* __restrict__ Wh) {
    __shared__ float sm[128][17];
    const int kg    = blockIdx.x;
    const int mtile = blockIdx.y;
    const int z     = blockIdx.z;
    const int wsel  = z >> 7;
    const int l     = (z >> 5) & 3;
    const int lcta  = z & 31;
    const float* src = (wsel ? Wh : Wx) + (size_t)l * W_DIM * G_DIM;
    const int col_base = (mtile >> 1) * W_DIM + lcta * 32 + (mtile & 1) * 16;
    const int kbase = kg * 128;
    const int tid = threadIdx.x;

    const int cc = tid & 15, krow = tid >> 4;
    #pragma unroll
    for (int rep = 0; rep < 8; ++rep) {
        int k = krow + rep * 16;
        sm[k][cc] = src[(size_t)(kbase + k) * G_DIM + col_base + cc];
    }
    __syncthreads();

    const int ksl = tid >> 5, lane = tid & 31;
    const int r = lane >> 2, c2 = (lane & 3) * 2;
    const int kl = ksl * 16 + c2;
    unsigned short h[8];
    h[0] = __half_as_ushort(__float2half(sm[kl    ][r]));
    h[1] = __half_as_ushort(__float2half(sm[kl + 1][r]));
    h[2] = __half_as_ushort(__float2half(sm[kl    ][r + 8]));
    h[3] = __half_as_ushort(__float2half(sm[kl + 1][r + 8]));
    h[4] = __half_as_ushort(__float2half(sm[kl + 8][r]));
    h[5] = __half_as_ushort(__float2half(sm[kl + 9][r]));
    h[6] = __half_as_ushort(__float2half(sm[kl + 8][r + 8]));
    h[7] = __half_as_ushort(__float2half(sm[kl + 9][r + 8]));
    uint4 q;
    q.x = (unsigned)h[0] | ((unsigned)h[1] << 16);
    q.y = (unsigned)h[2] | ((unsigned)h[3] << 16);
    q.z = (unsigned)h[4] | ((unsigned)h[5] << 16);
    q.w = (unsigned)h[6] | ((unsigned)h[7] << 16);
    g_Wfrag[(((size_t)z * 8 + mtile) * 64 + kg * 8 + ksl) * 32 + lane] = q;
}

__global__ void convert_x_kernel(const float* __restrict__ x) {
    __half* dst = &g_x16[0][0][0];
    int i = blockIdx.x * blockDim.x + threadIdx.x;
    if (i < L_DIM * T_STEPS) (&g_done[0][0])[i] = 0;     // reset flags EVERY launch
    #pragma unroll
    for (int r = 0; r < 8; ++r) {
        int idx = i + r * (gridDim.x * blockDim.x);
        if (idx < T_STEPS * B_DIM * W_DIM) dst[idx] = __float2half(x[idx]);
    }
}

__global__ __launch_bounds__(NT) void lstm_mma_kernel(
    const void*  __restrict__ resets_raw,
    const float* __restrict__ c0,
    const float* __restrict__ h0,
    const float* __restrict__ bias,
    float* __restrict__ out)
{
    extern __shared__ __align__(16) char pool[];
    __shared__ float mask_next[B_DIM];
    __shared__ int s_rmode;

    const int tid  = threadIdx.x;
    const int cta  = blockIdx.x;
    const int lane = tid & 31;
    const int w    = tid >> 5;        // 0..15
    const int grp  = cta >> 5;        // layer owned
    const int lcta = cta & 31;
    const int u0   = lcta * 32;
    const int ms   = w >> 2;          // M-slice 0..3
    const int ks   = w & 3;           // K-slice 0..3

    float* out_ys = out;
    float* out_cs = out + (size_t)T_STEPS * B_DIM * W_DIM;
    float* out_hs = out_cs + (size_t)L_DIM * B_DIM * W_DIM;

    if (tid == 0) {
        const unsigned char* rb = (const unsigned char*)resets_raw;
        int s1 = 0, s2 = 0, s3 = 0;
        for (int i = 0; i < T_STEPS * B_DIM; i += 4) { s1 += rb[i+1]; s2 += rb[i+2]; s3 += rb[i+3]; }
        s_rmode = (s1 > 0) ? 0 : ((s2 == 0 && s3 == 0) ? 1 : 2);
    }
    __syncthreads();
    const int rmode = s_rmode;

    const unsigned char* r8  = (const unsigned char*)resets_raw;
    const int*           r32 = (const int*)resets_raw;
    const float*         rf  = (const float*)resets_raw;
    #define KEEP(t, b) (rmode == 0 ? (r8[(t)*B_DIM+(b)] ? 0.0f : 1.0f) \
                      : rmode == 1 ? (r32[(t)*B_DIM+(b)] ? 0.0f : 1.0f) \
                                   : (rf[(t)*B_DIM+(b)] != 0.0f ? 0.0f : 1.0f))

    // ---- init: hm slot 0 = keep[0]*h0, c pre-masked ----
    for (int i = cta * NT + tid; i < L_DIM * B_DIM * W_DIM; i += NB * NT) {
        int b = (i >> 10) & 31;
        int l = i >> 15;
        float k0f = KEEP(0, b);
        (&g_hm[l][0][0][0])[i & 0x7FFF] = __float2half(k0f * h0[i]);
        (&g_c[0][0][0])[i]              = k0f * c0[i];
    }
    gridBarrier();   // one-time: init + flag reset visible everywhere

    const unsigned poolAddr = smem_u32(pool);
    float* red = (float*)(pool + RED_OFF);
    #define RED_IDX(kk, m, n) (((kk) * 128 + (m)) * 36 + (n))

    // ---- weight fragment bases ----
    const uint4* wbX = g_Wfrag + (((size_t)(0 * 4 + grp) * 32 + lcta) * 8) * 64 * 32;
    const uint4* wbH = g_Wfrag + (((size_t)(1 * 4 + grp) * 32 + lcta) * 8) * 64 * 32;
    unsigned fidx[2][2];
    #pragma unroll
    for (int mt = 0; mt < 2; ++mt)
        #pragma unroll
        for (int s = 0; s < 2; ++s)
            fidx[mt][s] = (unsigned)((((ms * 2 + mt) * 64) + ks * 2 + s) * 32 + lane);

    // ---- B staging ----
    const int bn  = tid >> 4;
    const int bkq = tid & 15;
    const unsigned bDst = (unsigned)((bn * ROWH + bkq * 8) * 2);
    const unsigned bSrc = (unsigned)(bn * W_DIM + bkq * 8);

    // ---- B ldmatrix offsets ----
    const int lrow8 = lane & 7;
    unsigned bRow[2];
    #pragma unroll
    for (int nt2 = 0; nt2 < 2; ++nt2)
        bRow[nt2] = (unsigned)((nt2 * 16 + lrow8 + ((lane >> 4) & 1) * 8) * ROWH * 2);
    const unsigned bKadj = (unsigned)(((lane >> 3) & 1) * 8 * 2);
    const unsigned kBase = (unsigned)(ks * 32 * 2);

    const int row = lane >> 2;
    const int kc2 = (lane & 3) * 2;

    volatile unsigned* doneFlat = (volatile unsigned*)&g_done[0][0];

    for (int t = 0; t < T_STEPS; ++t) {
        // ---- wait for producers (usually already satisfied) ----
        if (tid == 0) {
            if (grp > 0) while (doneFlat[(grp - 1) * T_STEPS + t] < 32u) { }
            if (t > 0)   while (doneFlat[grp * T_STEPS + (t - 1)] < 32u) { }
            __threadfence();
        }
        __syncthreads();

        if (tid < B_DIM)
            mask_next[tid] = (t + 1 < T_STEPS) ? KEEP(t + 1, tid) : 1.0f;

        const __half* ax = (grp == 0) ? &g_x16[t][0][0] : &g_hy[grp - 1][t][0][0];
        const __half* ah = &g_hm[grp][t][0][0];

        // prologue: stage B chunks 0..2
        cpa16(poolAddr + 0 * B_ST_BYTES + bDst, ax + bSrc);           CP_COMMIT();
        cpa16(poolAddr + 1 * B_ST_BYTES + bDst, ax + bSrc + KCH);     CP_COMMIT();
        cpa16(poolAddr + 2 * B_ST_BYTES + bDst, ax + bSrc + 2 * KCH); CP_COMMIT();

        // prologue: A fragments chunk 0
        uint4 afrag[2][4];
        #pragma unroll
        for (int f = 0; f < 4; ++f)
            afrag[0][f] = wbX[fidx[f >> 1][f & 1]];

        float acc[2][4][4];
        #pragma unroll
        for (int mt = 0; mt < 2; ++mt)
            #pragma unroll
            for (int nt = 0; nt < 4; ++nt)
                #pragma unroll
                for (int q = 0; q < 4; ++q) acc[mt][nt][q] = 0.0f;

        for (int c = 0; c < NCH; ++c) {
            if (c + 1 < NCH) {
                const int cn = c + 1;
                const uint4* wb = (cn < 8) ? wbX : wbH;
                const unsigned co = (unsigned)((cn & 7) * 256);
                #pragma unroll
                for (int f = 0; f < 4; ++f)
                    afrag[cn & 1][f] = wb[co + fidx[f >> 1][f & 1]];
            }

            if (c <= NCH - 3)      asm volatile("cp.async.wait_group 2;" ::: "memory");
            else if (c == NCH - 2) asm volatile("cp.async.wait_group 1;" ::: "memory");
            else                   asm volatile("cp.async.wait_group 0;" ::: "memory");
            __syncthreads();

            if (c + 3 < NCH) {
                const int cn = c + 3;
                const __half* ab = (cn < 8) ? ax : ah;
                cpa16(poolAddr + (cn & 3) * B_ST_BYTES + bDst,
                      ab + bSrc + (cn & 7) * KCH);
                CP_COMMIT();
            }

            const unsigned bsb = poolAddr + (c & 3) * B_ST_BYTES;
            #pragma unroll
            for (int s = 0; s < 2; ++s) {
                const unsigned kOff = kBase + (unsigned)(s * 16 * 2);
                unsigned b0[4], b1[4];
                LDSM4(b0[0], b0[1], b0[2], b0[3], bsb + bRow[0] + kOff + bKadj);
                LDSM4(b1[0], b1[1], b1[2], b1[3], bsb + bRow[1] + kOff + bKadj);
                #pragma unroll
                for (int mt = 0; mt < 2; ++mt) {
                    const uint4 q = afrag[c & 1][mt * 2 + s];
                    mma_f16(acc[mt][0][0], acc[mt][0][1], acc[mt][0][2], acc[mt][0][3],
                            q.x, q.y, q.z, q.w, b0[0], b0[1]);
                    mma_f16(acc[mt][1][0], acc[mt][1][1], acc[mt][1][2], acc[mt][1][3],
                            q.x, q.y, q.z, q.w, b0[2], b0[3]);
                    mma_f16(acc[mt][2][0], acc[mt][2][1], acc[mt][2][2], acc[mt][2][3],
                            q.x, q.y, q.z, q.w, b1[0], b1[1]);
                    mma_f16(acc[mt][3][0], acc[mt][3][1], acc[mt][3][2], acc[mt][3][3],
                            q.x, q.y, q.z, q.w, b1[2], b1[3]);
                }
            }
        }

        // ---- k-slice partial exchange ----
        #pragma unroll
        for (int mt = 0; mt < 2; ++mt)
            #pragma unroll
            for (int nt = 0; nt < 4; ++nt) {
                const int m_r = ms * 32 + mt * 16 + row;
                const int n0  = nt * 8 + kc2;
                *(float2*)&red[RED_IDX(ks, m_r, n0)] =
                    make_float2(acc[mt][nt][0], acc[mt][nt][1]);
                *(float2*)&red[RED_IDX(ks, m_r + 8, n0)] =
                    make_float2(acc[mt][nt][2], acc[mt][nt][3]);
            }
        __syncthreads();

        // ---- reduce + bias + LSTM pointwise ----
        {
            const int u  = tid & 31;
            const int np = tid >> 5;
            const int ug = u0 + u;
            #pragma unroll
            for (int e = 0; e < 2; ++e) {
                const int n = np * 2 + e;
                float gate[4];
                #pragma unroll
                for (int g = 0; g < 4; ++g) {
                    const int m = g * 32 + u;
                    gate[g] = red[RED_IDX(0, m, n)] + red[RED_IDX(1, m, n)]
                            + red[RED_IDX(2, m, n)] + red[RED_IDX(3, m, n)]
                            + bias[grp * G_DIM + g * W_DIM + ug];
                }
                float cOld = g_c[grp][n][ug];
                float cN = sigmoidf_(gate[1]) * cOld + sigmoidf_(gate[0]) * tanhf(gate[2]);
                float hN = sigmoidf_(gate[3]) * tanhf(cN);
                float keepN = mask_next[n];

                g_c[grp][n][ug] = keepN * cN;
                g_hy[grp][t][n][ug]     = __float2half(hN);
                g_hm[grp][t + 1][n][ug] = __float2half(keepN * hN);
                if (grp == L_DIM - 1)
                    out_ys[((size_t)t * B_DIM + n) * W_DIM + ug] = hN;
                if (t == T_STEPS - 1) {
                    out_cs[((size_t)grp * B_DIM + n) * W_DIM + ug] = cN;
                    out_hs[((size_t)grp * B_DIM + n) * W_DIM + ug] = hN;
                }
            }
        }

        // ---- signal consumers ----
        __syncthreads();
        if (tid == 0) {
            __threadfence();
            atomicAdd((unsigned*)&g_done[grp][t], 1u);
        }
    }
    #undef KEEP
    #undef RED_IDX
}

extern "C" void kernel_launch(void* const* d_in, const int* in_sizes, int n_in,
                              void* d_out, int out_size) {
    const float* x      = (const float*)d_in[0];
    const void*  resets = (const void*) d_in[1];
    const float* c0     = (const float*)d_in[2];
    const float* h0     = (const float*)d_in[3];
    const float* Wx     = (const float*)d_in[4];
    const float* Wh     = (const float*)d_in[5];
    const float* b      = (const float*)d_in[6];
    (void)in_sizes; (void)n_in; (void)out_size;

    static int configured = 0;
    if (!configured) {
        cudaFuncSetAttribute(lstm_mma_kernel, cudaFuncAttributeMaxDynamicSharedMemorySize, DYN_BYTES);
        configured = 1;
    }

    convert_wfrag_kernel<<<dim3(8, 8, 256), 256>>>(Wx, Wh);
    convert_x_kernel<<<1024, 256>>>(x);
    lstm_mma_kernel<<<NB, NT, DYN_BYTES>>>(resets, c0, h0, b, (float*)d_out);
}